// round 6
// baseline (speedup 1.0000x reference)
#include <cuda_runtime.h>

#define NB 4
#define NC 64
#define HW 40
#define KS 11
#define HP 30
#define PIX 1600          // 40*40
#define PW  112           // padded im2 row width in smem
#define POFF 32           // left pad
#define SLAB (HW*PW)      // one channel slab in smem
#define NDX 15            // dx shifts per block (groups: 15+15+15+14 live)
#define NG 8              // norm partial groups
#define OUTN (NB*HP*HP)

__device__ unsigned g_enc[OUTN];
__device__ float    g_inv[OUTN];
__device__ float    g_part[NB*NG*PIX];

__device__ __forceinline__ unsigned encf(float f){
    int b = __float_as_int(f);
    return (unsigned)(b ^ ((b >> 31) | 0x80000000));
}

// ---------------- K0a: partial channel sum-of-squares ----------------
__global__ void __launch_bounds__(256) norm_part(const float* __restrict__ im1){
    int b = blockIdx.x, g = blockIdx.y;
    const float* base = im1 + ((size_t)b*NC + g*(NC/NG))*PIX;
    for (int p = threadIdx.x; p < PIX; p += 256){
        float acc = 0.f;
        #pragma unroll
        for (int c = 0; c < NC/NG; ++c){ float v = base[c*PIX + p]; acc += v*v; }
        g_part[(b*NG + g)*PIX + p] = acc;
    }
}

// ---------------- K0b: reduce partials + 11x11 box sum -> inv norm ----------------
__global__ void __launch_bounds__(1024) norm_reduce(){
    __shared__ float sA[PIX];
    __shared__ float sH[HW*HP];
    int b = blockIdx.x;
    int tid = threadIdx.x;
    for (int p = tid; p < PIX; p += 1024){
        float acc = 0.f;
        #pragma unroll
        for (int g = 0; g < NG; ++g) acc += g_part[(b*NG + g)*PIX + p];
        sA[p] = acc;
    }
    __syncthreads();
    for (int t = tid; t < HW*HP; t += 1024){
        int y = t / HP, lx = t - y*HP;
        const float* row = &sA[y*HW];
        float s = 0.f;
        #pragma unroll
        for (int j = 0; j < KS; ++j) s += row[lx + j];
        sH[y*HP + lx] = s;
    }
    __syncthreads();
    for (int t = tid; t < HP*HP; t += 1024){
        int ly = t / HP, lx = t - ly*HP;
        float s = 0.f;
        #pragma unroll
        for (int i = 0; i < KS; ++i) s += sH[(ly+i)*HP + lx];
        float nrm = sqrtf(s);
        g_inv[b*HP*HP + t] = 1.0f / fmaxf(nrm, 1e-4f);
        g_enc[b*HP*HP + t] = 0u;
    }
}

// ---------------- one channel of correlation accumulation ----------------
// q[d*4+j] += A[j] * w[SH+d+j], w = cur[a0 .. a0+23]
template<int SH>
__device__ __forceinline__ void comp_channel(const float* __restrict__ cur, int a0,
                                             float4 A, float* __restrict__ q){
    float w[24];
    #pragma unroll
    for (int k = 0; k < 6; ++k){
        float4 tv = *(const float4*)&cur[a0 + 4*k];
        w[4*k+0]=tv.x; w[4*k+1]=tv.y; w[4*k+2]=tv.z; w[4*k+3]=tv.w;
    }
    #pragma unroll
    for (int d = 0; d < NDX; ++d){
        q[d*4+0] += A.x * w[SH+d+0];
        q[d*4+1] += A.y * w[SH+d+1];
        q[d*4+2] += A.z * w[SH+d+2];
        q[d*4+3] += A.w * w[SH+d+3];
    }
}

// ---------------- corr mainloop: 2 channels per barrier phase ----------------
// SH = 3 + ((dxlo-3)&3): g0->3, g1->6, g2->5, g3->4
template<int SH>
__device__ __forceinline__ void run_channels(
    const float* __restrict__ g1, const float* __restrict__ g2,
    float* __restrict__ bufA, float* __restrict__ bufB,
    float* __restrict__ q,
    int tid, int n4, int a0, int d2)
{
    bool ld = (tid < n4);
    float4 z = make_float4(0,0,0,0);
    float4 a0r=z, a1r=z, a2r=z, a3r=z, w2r=z, w3r=z;

    if (ld){
        float4 w0 = ((const float4*)g2)[tid];
        float4 w1 = ((const float4*)(g2 + PIX))[tid];
        *(float4*)&bufA[d2]        = w0;
        *(float4*)&bufA[SLAB + d2] = w1;
        a0r = ((const float4*)g1)[tid];
        a1r = ((const float4*)(g1 +   PIX))[tid];
        a2r = ((const float4*)(g1 + 2*PIX))[tid];
        a3r = ((const float4*)(g1 + 3*PIX))[tid];
        w2r = ((const float4*)(g2 + 2*PIX))[tid];
        w3r = ((const float4*)(g2 + 3*PIX))[tid];
    }
    __syncthreads();   // pair 0 staged; pads zeroed

    #pragma unroll 1
    for (int c = 0; c < NC; c += 2){
        float* cur = (c & 2) ? bufB : bufA;
        float* nxt = (c & 2) ? bufA : bufB;

        if (ld){
            if (c + 2 < NC){                       // stage next pair
                *(float4*)&nxt[d2]        = w2r;
                *(float4*)&nxt[SLAB + d2] = w3r;
            }
            if (c + 4 < NC){                       // prefetch pair c+4,c+5
                w2r = ((const float4*)(g2 + (c+4)*PIX))[tid];
                w3r = ((const float4*)(g2 + (c+5)*PIX))[tid];
            }
            comp_channel<SH>(cur,        a0, a0r, q);
            comp_channel<SH>(cur + SLAB, a0, a1r, q);
            a0r = a2r; a1r = a3r;
            if (c + 4 < NC){
                a2r = ((const float4*)(g1 + (c+4)*PIX))[tid];
                a3r = ((const float4*)(g1 + (c+5)*PIX))[tid];
            }
        }
        __syncthreads();   // reads of cur done before it becomes nxt
    }
}

// ---------------- K1: displacement correlation + box sums + max ----------------
// grid: (4 dx-groups, 59 dy, 4 batch), 512 threads
__global__ void __launch_bounds__(512, 1) corr_kernel(const float* __restrict__ im1,
                                                      const float* __restrict__ im2){
    extern __shared__ float smem[];
    float* bufA = smem;                   // [2*SLAB] channels pair (zero-padded)
    float* bufB = bufA + 2*SLAB;          // [2*SLAB]
    float* sq   = bufB + 2*SLAB;          // [NDX*1600]
    float* sinv = sq + NDX*PIX;           // [900]

    int tid  = threadIdx.x;
    int gx   = blockIdx.x;
    int b    = blockIdx.z;
    int dy   = (int)blockIdx.y - 29;
    int dxlo = -29 + NDX*gx;

    // zero all four padded slabs; load inv-norm
    for (int i = tid; i < (4*SLAB)/4; i += 512)
        ((float4*)bufA)[i] = make_float4(0.f,0.f,0.f,0.f);
    for (int i = tid; i < HP*HP; i += 512) sinv[i] = g_inv[b*HP*HP + i];

    int y0 = max(0, -dy), y1 = min(HW, HW - dy);
    int nrows = y1 - y0;
    int n4 = nrows * 10;                  // active float4 strips

    int sy = y0 + tid/10;
    int sx = (tid - (tid/10)*10) * 4;
    int i1 = sy*HW + sx;

    const float* g1 = im1 + (size_t)b*NC*PIX + y0*HW;
    const float* g2 = im2 + (size_t)b*NC*PIX + (y0+dy)*HW;

    int r2row = tid/10;
    int d2 = (y0+dy+r2row)*PW + POFF + (tid - r2row*10)*4;

    float q[NDX*4];
    #pragma unroll
    for (int i = 0; i < NDX*4; ++i) q[i] = 0.f;

    int base2 = (sy+dy)*PW + POFF + sx + dxlo;
    switch (gx){
        case 0: run_channels<3>(g1,g2,bufA,bufB,q,tid,n4,base2-3,d2); break;
        case 1: run_channels<6>(g1,g2,bufA,bufB,q,tid,n4,base2-6,d2); break;
        case 2: run_channels<5>(g1,g2,bufA,bufB,q,tid,n4,base2-5,d2); break;
        default: run_channels<4>(g1,g2,bufA,bufB,q,tid,n4,base2-4,d2); break;
    }

    // dump accumulators
    if (tid < n4){
        #pragma unroll
        for (int d = 0; d < NDX; ++d)
            *(float4*)&sq[d*PIX + i1] = make_float4(q[d*4+0],q[d*4+1],q[d*4+2],q[d*4+3]);
    }
    __syncthreads();

    // horizontal 11-sum (in place, cols 0..29)
    for (int t = tid; t < NDX*nrows; t += 512){
        int d = t / nrows;
        int y = y0 + (t - d*nrows);
        float* row = &sq[d*PIX + y*HW];
        float r[HW];
        #pragma unroll
        for (int k = 0; k < HW/4; ++k){
            float4 tv = *(const float4*)&row[4*k];
            r[4*k+0]=tv.x; r[4*k+1]=tv.y; r[4*k+2]=tv.z; r[4*k+3]=tv.w;
        }
        float s = 0.f;
        #pragma unroll
        for (int j = 0; j < KS; ++j) s += r[j];
        row[0] = s;
        #pragma unroll
        for (int lx = 1; lx < HP; ++lx){
            s += r[lx+KS-1] - r[lx-1];
            row[lx] = s;
        }
    }
    __syncthreads();

    // vertical 11-sum (in place)
    int ly0 = max(0, -dy);
    int nly = min(HP, HP - dy) - ly0;
    for (int t = tid; t < NDX*HP; t += 512){
        int d = t / HP, lx = t - (t/HP)*HP;
        float* colp = &sq[d*PIX + lx];
        int cnt = nly + KS - 1;
        float v[HW];
        #pragma unroll
        for (int i = 0; i < HW; ++i) v[i] = (i < cnt) ? colp[(ly0+i)*HW] : 0.f;
        float s = 0.f;
        #pragma unroll
        for (int j = 0; j < KS; ++j) s += v[j];
        #pragma unroll
        for (int o = 0; o < HP; ++o){
            if (o < nly) colp[(ly0+o)*HW] = s;
            if (o+1 < HP) s += v[o+KS] - v[o];
        }
    }
    __syncthreads();

    // per-output max over this block's dx set, one atomicMax per p
    unsigned* eout = &g_enc[b*HP*HP];
    for (int t = tid; t < HP*HP; t += 512){
        int py = t / HP, px = t - (t/HP)*HP;
        int ly = py - dy;
        if (ly < 0 || ly >= HP) continue;
        float m = -3.0e38f;
        bool any = false;
        #pragma unroll
        for (int d = 0; d < NDX; ++d){
            int dx = dxlo + d;
            int lx = px - dx;
            if (dx <= 29 && lx >= 0 && lx < HP){
                float v = sq[d*PIX + ly*HW + lx] * sinv[ly*HP + lx];
                m = fmaxf(m, v);
                any = true;
            }
        }
        if (any) atomicMax(&eout[t], encf(m));
    }
}

// ---------------- K2: decode ----------------
__global__ void decode_kernel(float* __restrict__ out){
    int t = blockIdx.x*blockDim.x + threadIdx.x;
    if (t < OUTN){
        unsigned e = g_enc[t];
        int v = (e & 0x80000000u) ? (int)(e ^ 0x80000000u) : ~(int)e;
        out[t] = __int_as_float(v);
    }
}

extern "C" void kernel_launch(void* const* d_in, const int* in_sizes, int n_in,
                              void* d_out, int out_size){
    (void)in_sizes; (void)n_in; (void)out_size;
    const float* im1 = (const float*)d_in[0];
    const float* im2 = (const float*)d_in[1];

    const int smem_bytes = (4*SLAB + NDX*PIX + HP*HP) * (int)sizeof(float);
    cudaFuncSetAttribute(corr_kernel, cudaFuncAttributeMaxDynamicSharedMemorySize, smem_bytes);

    norm_part<<<dim3(NB, NG), 256>>>(im1);
    norm_reduce<<<NB, 1024>>>();
    corr_kernel<<<dim3(4, 59, NB), 512, smem_bytes>>>(im1, im2);
    decode_kernel<<<(OUTN + 255)/256, 256>>>((float*)d_out);
}

// round 8
// speedup vs baseline: 1.6170x; 1.6170x over previous
#include <cuda_runtime.h>

#define NB 4
#define NC 64
#define HW 40
#define KS 11
#define HP 30
#define PIX 1600          // 40*40
#define PW  112           // padded im2 row width in smem
#define POFF 32           // left pad
#define SLAB (HW*PW)
#define NDX 15            // dx shifts per block (4 groups; last has 14 live)
#define NG 8
#define OUTN (NB*HP*HP)

__device__ unsigned g_enc[OUTN];
__device__ float    g_inv[OUTN];
__device__ float    g_part[NB*NG*PIX];

__device__ __forceinline__ unsigned encf(float f){
    int b = __float_as_int(f);
    return (unsigned)(b ^ ((b >> 31) | 0x80000000));
}

// ---------------- K0a: partial channel sum-of-squares ----------------
__global__ void __launch_bounds__(256) norm_part(const float* __restrict__ im1){
    int b = blockIdx.x, g = blockIdx.y;
    const float* base = im1 + ((size_t)b*NC + g*(NC/NG))*PIX;
    for (int p = threadIdx.x; p < PIX; p += 256){
        float acc = 0.f;
        #pragma unroll
        for (int c = 0; c < NC/NG; ++c){ float v = base[c*PIX + p]; acc += v*v; }
        g_part[(b*NG + g)*PIX + p] = acc;
    }
}

// ---------------- K0b: reduce partials + 11x11 box sum -> inv norm ----------------
__global__ void __launch_bounds__(1024) norm_reduce(){
    __shared__ float sA[PIX];
    __shared__ float sH[HW*HP];
    int b = blockIdx.x;
    int tid = threadIdx.x;
    for (int p = tid; p < PIX; p += 1024){
        float acc = 0.f;
        #pragma unroll
        for (int g = 0; g < NG; ++g) acc += g_part[(b*NG + g)*PIX + p];
        sA[p] = acc;
    }
    __syncthreads();
    for (int t = tid; t < HW*HP; t += 1024){
        int y = t / HP, lx = t - y*HP;
        const float* row = &sA[y*HW];
        float s = 0.f;
        #pragma unroll
        for (int j = 0; j < KS; ++j) s += row[lx + j];
        sH[y*HP + lx] = s;
    }
    __syncthreads();
    for (int t = tid; t < HP*HP; t += 1024){
        int ly = t / HP, lx = t - ly*HP;
        float s = 0.f;
        #pragma unroll
        for (int i = 0; i < KS; ++i) s += sH[(ly+i)*HP + lx];
        float nrm = sqrtf(s);
        g_inv[b*HP*HP + t] = 1.0f / fmaxf(nrm, 1e-4f);
        g_enc[b*HP*HP + t] = 0u;
    }
}

// ---------------- one channel: q[d*4+j] += A[j] * cur[a0 + SH + d + j] ----------------
template<int SH>
__device__ __forceinline__ void comp_channel(const float* __restrict__ cur, int a0,
                                             float4 A, float* __restrict__ q){
    float w[24];
    #pragma unroll
    for (int k = 0; k < 6; ++k){
        float4 tv = *(const float4*)&cur[a0 + 4*k];
        w[4*k+0]=tv.x; w[4*k+1]=tv.y; w[4*k+2]=tv.z; w[4*k+3]=tv.w;
    }
    #pragma unroll
    for (int d = 0; d < NDX; ++d){
        q[d*4+0] += A.x * w[SH+d+0];
        q[d*4+1] += A.y * w[SH+d+1];
        q[d*4+2] += A.z * w[SH+d+2];
        q[d*4+3] += A.w * w[SH+d+3];
    }
}

// ---------------- mainloop: double-buffered im2 slab, 1 barrier/channel ----------------
template<int SH>
__device__ __forceinline__ void run_channels(
    const float* __restrict__ g1, const float* __restrict__ g2,
    float* __restrict__ buf0, float* __restrict__ buf1,
    float* __restrict__ q,
    int i1, int a0, int d2, int tsrc, bool act, bool stg)
{
    float4 z = make_float4(0.f,0.f,0.f,0.f);
    float4 aCur=z, aNxt=z, wNxt=z;
    if (stg){
        *(float4*)&buf0[d2] = *(const float4*)&g2[tsrc];      // ch0
        wNxt = *(const float4*)&g2[PIX + tsrc];               // ch1
    }
    if (act){
        aCur = *(const float4*)&g1[i1];
        aNxt = *(const float4*)&g1[PIX + i1];
    }
    __syncthreads();

    #pragma unroll 1
    for (int c = 0; c < NC; ++c){
        const float* cur = (c & 1) ? buf1 : buf0;
        float* nxt = (c & 1) ? buf0 : buf1;
        if (c + 1 < NC && stg) *(float4*)&nxt[d2] = wNxt;
        float4 aP = aNxt;
        if (c + 2 < NC){
            if (act) aNxt = *(const float4*)&g1[(c+2)*PIX + i1];
            if (stg) wNxt = *(const float4*)&g2[(c+2)*PIX + tsrc];
        }
        if (act) comp_channel<SH>(cur, a0, aCur, q);
        aCur = aP;
        __syncthreads();
    }
}

// ---------------- epilogue for one dy: dump, box sums, max+atomic ----------------
__device__ void do_epi(float* __restrict__ sq, const float* __restrict__ sinv,
                       unsigned* __restrict__ eout, const float* __restrict__ q,
                       bool mine, int i1, int dy, int dxlo, int tid)
{
    if (mine){
        #pragma unroll
        for (int d = 0; d < NDX; ++d)
            *(float4*)&sq[d*PIX + i1] = make_float4(q[d*4+0],q[d*4+1],q[d*4+2],q[d*4+3]);
    }
    __syncthreads();

    int ady = (dy < 0) ? -dy : dy;
    int y0  = (dy < 0) ? -dy : 0;
    int nrows = HW - ady;

    // horizontal 11-sum (in place, cols 0..29)
    for (int t = tid; t < NDX*nrows; t += 512){
        int d = t / nrows;
        int y = y0 + (t - d*nrows);
        float* row = &sq[d*PIX + y*HW];
        float r[HW];
        #pragma unroll
        for (int k = 0; k < HW/4; ++k){
            float4 tv = *(const float4*)&row[4*k];
            r[4*k+0]=tv.x; r[4*k+1]=tv.y; r[4*k+2]=tv.z; r[4*k+3]=tv.w;
        }
        float s = 0.f;
        #pragma unroll
        for (int j = 0; j < KS; ++j) s += r[j];
        row[0] = s;
        #pragma unroll
        for (int lx = 1; lx < HP; ++lx){
            s += r[lx+KS-1] - r[lx-1];
            row[lx] = s;
        }
    }
    __syncthreads();

    // vertical 11-sum (in place)
    int ly0 = y0;
    int nly = HP - ady;
    for (int t = tid; t < NDX*HP; t += 512){
        int d = t / HP, lx = t - (t/HP)*HP;
        float* colp = &sq[d*PIX + lx];
        int cnt = nly + KS - 1;
        float v[HW];
        #pragma unroll
        for (int i = 0; i < HW; ++i) v[i] = (i < cnt) ? colp[(ly0+i)*HW] : 0.f;
        float s = 0.f;
        #pragma unroll
        for (int j = 0; j < KS; ++j) s += v[j];
        #pragma unroll
        for (int o = 0; o < HP; ++o){
            if (o < nly) colp[(ly0+o)*HW] = s;
            if (o+1 < HP) s += v[o+KS] - v[o];
        }
    }
    __syncthreads();

    // per-output max over this block's dx set, one atomicMax per p
    for (int t = tid; t < HP*HP; t += 512){
        int py = t / HP, px = t - (t/HP)*HP;
        int ly = py - dy;
        if (ly < 0 || ly >= HP) continue;
        float m = -3.0e38f;
        bool any = false;
        #pragma unroll
        for (int d = 0; d < NDX; ++d){
            int dx = dxlo + d;
            int lx = px - dx;
            if (dx <= 29 && lx >= 0 && lx < HP){
                float v = sq[d*PIX + ly*HW + lx] * sinv[ly*HP + lx];
                m = fmaxf(m, v);
                any = true;
            }
        }
        if (any) atomicMax(&eout[t], encf(m));
    }
    __syncthreads();   // sq free for next pass
}

// ---------------- K1: paired-dy correlation ----------------
// grid: (4 dx-groups, 30 dy-pairs, 4 batch), 512 threads
__global__ void __launch_bounds__(512, 1) corr_kernel(const float* __restrict__ im1,
                                                      const float* __restrict__ im2){
    extern __shared__ float smem[];
    float* buf0 = smem;                  // [SLAB] im2 channel (zero-padded)
    float* buf1 = buf0 + SLAB;           // [SLAB]
    float* sq   = buf1 + SLAB;           // [NDX*1600]
    float* sinv = sq + NDX*PIX;          // [900]

    int tid = threadIdx.x;
    int gx  = blockIdx.x;
    int p   = blockIdx.y;
    int b   = blockIdx.z;
    int dxlo = -29 + NDX*gx;

    int dyA, dyB, cntA, cntB;
    if (p < 29){ dyA = p - 29; dyB = p + 1; cntA = (11+p)*10; cntB = (39-p)*10; }
    else       { dyA = 0;      dyB = 0;     cntA = 400;       cntB = 0;        }

    // zero both slabs (pads stay zero forever); load inv-norm
    for (int i = tid; i < (2*SLAB)/4; i += 512)
        ((float4*)buf0)[i] = make_float4(0.f,0.f,0.f,0.f);
    for (int i = tid; i < HP*HP; i += 512) sinv[i] = g_inv[b*HP*HP + i];

    bool act = tid < cntA + cntB;
    int myDy, s;
    if (tid < cntA){ myDy = dyA; s = tid; } else { myDy = dyB; s = tid - cntA; }
    int y0t = (myDy < 0) ? -myDy : 0;
    int sy = y0t + s/10;
    int sx = (s - (s/10)*10)*4;
    int i1 = sy*HW + sx;

    const float* g1 = im1 + (size_t)b*NC*PIX;
    const float* g2 = im2 + (size_t)b*NC*PIX;

    bool stg = tid < 400;                      // stage all 40 im2 rows
    int r2 = tid/10;
    int d2 = r2*PW + POFF + (tid - r2*10)*4;
    int tsrc = tid*4;

    float q[NDX*4];
    #pragma unroll
    for (int i = 0; i < NDX*4; ++i) q[i] = 0.f;

    int base2 = (sy + myDy)*PW + POFF + sx + dxlo;
    switch (gx){
        case 0: run_channels<3>(g1,g2,buf0,buf1,q,i1,base2-3,d2,tsrc,act,stg); break;
        case 1: run_channels<6>(g1,g2,buf0,buf1,q,i1,base2-6,d2,tsrc,act,stg); break;
        case 2: run_channels<5>(g1,g2,buf0,buf1,q,i1,base2-5,d2,tsrc,act,stg); break;
        default: run_channels<4>(g1,g2,buf0,buf1,q,i1,base2-4,d2,tsrc,act,stg); break;
    }

    unsigned* eout = &g_enc[b*HP*HP];
    do_epi(sq, sinv, eout, q, tid < cntA, i1, dyA, dxlo, tid);
    if (cntB > 0)
        do_epi(sq, sinv, eout, q, act && tid >= cntA, i1, dyB, dxlo, tid);
}

// ---------------- K2: decode ----------------
__global__ void decode_kernel(float* __restrict__ out){
    int t = blockIdx.x*blockDim.x + threadIdx.x;
    if (t < OUTN){
        unsigned e = g_enc[t];
        int v = (e & 0x80000000u) ? (int)(e ^ 0x80000000u) : ~(int)e;
        out[t] = __int_as_float(v);
    }
}

extern "C" void kernel_launch(void* const* d_in, const int* in_sizes, int n_in,
                              void* d_out, int out_size){
    (void)in_sizes; (void)n_in; (void)out_size;
    const float* im1 = (const float*)d_in[0];
    const float* im2 = (const float*)d_in[1];

    const int smem_bytes = (2*SLAB + NDX*PIX + HP*HP) * (int)sizeof(float);
    cudaFuncSetAttribute(corr_kernel, cudaFuncAttributeMaxDynamicSharedMemorySize, smem_bytes);

    norm_part<<<dim3(NB, NG), 256>>>(im1);
    norm_reduce<<<NB, 1024>>>();
    corr_kernel<<<dim3(4, 30, NB), 512, smem_bytes>>>(im1, im2);
    decode_kernel<<<(OUTN + 255)/256, 256>>>((float*)d_out);
}

// round 9
// speedup vs baseline: 2.1434x; 1.3255x over previous
#include <cuda_runtime.h>

#define NB 4
#define NC 64
#define HW 40
#define KS 11
#define HP 30
#define PIX 1600          // 40*40
#define NDX 15            // dx shifts per block (4 groups; last has 14 live)
#define NG 8
#define GUARD 64          // floats of guard padding each side of im2 copy
#define OUTN (NB*HP*HP)

__device__ unsigned g_enc[OUTN];
__device__ float    g_inv[OUTN];
__device__ float    g_part[NB*NG*PIX];
__device__ __align__(16) float g_im2g[GUARD + NB*NC*PIX + GUARD];

__device__ __forceinline__ unsigned encf(float f){
    int b = __float_as_int(f);
    return (unsigned)(b ^ ((b >> 31) | 0x80000000));
}

// ---------------- K0a: blocks 0..31 partial sum-of-squares, 32..63 guarded im2 copy ----
__global__ void __launch_bounds__(256) prep_kernel(const float* __restrict__ im1,
                                                   const float* __restrict__ im2){
    int blk = blockIdx.x;
    if (blk < NB*NG){
        int b = blk >> 3, g = blk & 7;
        const float* base = im1 + ((size_t)b*NC + g*(NC/NG))*PIX;
        for (int p = threadIdx.x; p < PIX; p += 256){
            float acc = 0.f;
            #pragma unroll
            for (int c = 0; c < NC/NG; ++c){ float v = base[c*PIX + p]; acc += v*v; }
            g_part[(b*NG + g)*PIX + p] = acc;
        }
    } else {
        int cb = blk - NB*NG;                  // 0..31
        const int total4 = (NB*NC*PIX)/4;      // 102400 float4
        const float4* src = (const float4*)im2;
        float4* dst = (float4*)(g_im2g + GUARD);
        for (int i = cb*256 + threadIdx.x; i < total4; i += 32*256)
            dst[i] = src[i];
        // zero guards (block 32 only)
        if (cb == 0){
            for (int i = threadIdx.x; i < GUARD; i += 256){
                g_im2g[i] = 0.f;
                g_im2g[GUARD + NB*NC*PIX + i] = 0.f;
            }
        }
    }
}

// ---------------- K0b: reduce partials + 11x11 box sum -> inv norm ----------------
__global__ void __launch_bounds__(1024) norm_reduce(){
    __shared__ float sA[PIX];
    __shared__ float sH[HW*HP];
    int b = blockIdx.x;
    int tid = threadIdx.x;
    for (int p = tid; p < PIX; p += 1024){
        float acc = 0.f;
        #pragma unroll
        for (int g = 0; g < NG; ++g) acc += g_part[(b*NG + g)*PIX + p];
        sA[p] = acc;
    }
    __syncthreads();
    for (int t = tid; t < HW*HP; t += 1024){
        int y = t / HP, lx = t - y*HP;
        const float* row = &sA[y*HW];
        float s = 0.f;
        #pragma unroll
        for (int j = 0; j < KS; ++j) s += row[lx + j];
        sH[y*HP + lx] = s;
    }
    __syncthreads();
    for (int t = tid; t < HP*HP; t += 1024){
        int ly = t / HP, lx = t - ly*HP;
        float s = 0.f;
        #pragma unroll
        for (int i = 0; i < KS; ++i) s += sH[(ly+i)*HP + lx];
        float nrm = sqrtf(s);
        g_inv[b*HP*HP + t] = 1.0f / fmaxf(nrm, 1e-4f);
        g_enc[b*HP*HP + t] = 0u;
    }
}

// ---------------- mainloop: direct-LDG, zero barriers ----------------
// q[d*4+j] += A[j] * W[col = x + dxlo + d], W window w[SH+d+j]
template<int SH>
__device__ __forceinline__ void run_channels(
    const float* __restrict__ g1c,    // &im1[b][0][i1]
    const float* __restrict__ wpc,    // guarded im2 ptr at window start (16B aligned)
    float* __restrict__ q)
{
    #pragma unroll 1
    for (int c = 0; c < NC; ++c){
        float4 A = __ldg((const float4*)(g1c + (size_t)c*PIX));
        float w[24];
        #pragma unroll
        for (int k = 0; k < 6; ++k){
            float4 tv = __ldg((const float4*)(wpc + (size_t)c*PIX + 4*k));
            w[4*k+0]=tv.x; w[4*k+1]=tv.y; w[4*k+2]=tv.z; w[4*k+3]=tv.w;
        }
        #pragma unroll
        for (int d = 0; d < NDX; ++d){
            q[d*4+0] += A.x * w[SH+d+0];
            q[d*4+1] += A.y * w[SH+d+1];
            q[d*4+2] += A.z * w[SH+d+2];
            q[d*4+3] += A.w * w[SH+d+3];
        }
    }
}

// ---------------- epilogue for one dy: dump, box sums, max+atomic ----------------
__device__ void do_epi(float* __restrict__ sq, const float* __restrict__ sinv,
                       unsigned* __restrict__ eout, const float* __restrict__ q,
                       bool mine, int i1, int dy, int dxlo, int tid)
{
    if (mine){
        #pragma unroll
        for (int d = 0; d < NDX; ++d)
            *(float4*)&sq[d*PIX + i1] = make_float4(q[d*4+0],q[d*4+1],q[d*4+2],q[d*4+3]);
    }
    __syncthreads();

    int ady = (dy < 0) ? -dy : dy;
    int y0  = (dy < 0) ? -dy : 0;
    int nrows = HW - ady;

    // horizontal 11-sum (in place, cols 0..29)
    for (int t = tid; t < NDX*nrows; t += 512){
        int d = t / nrows;
        int y = y0 + (t - d*nrows);
        float* row = &sq[d*PIX + y*HW];
        float r[HW];
        #pragma unroll
        for (int k = 0; k < HW/4; ++k){
            float4 tv = *(const float4*)&row[4*k];
            r[4*k+0]=tv.x; r[4*k+1]=tv.y; r[4*k+2]=tv.z; r[4*k+3]=tv.w;
        }
        float s = 0.f;
        #pragma unroll
        for (int j = 0; j < KS; ++j) s += r[j];
        row[0] = s;
        #pragma unroll
        for (int lx = 1; lx < HP; ++lx){
            s += r[lx+KS-1] - r[lx-1];
            row[lx] = s;
        }
    }
    __syncthreads();

    // vertical 11-sum (in place)
    int ly0 = y0;
    int nly = HP - ady;
    for (int t = tid; t < NDX*HP; t += 512){
        int d = t / HP, lx = t - (t/HP)*HP;
        float* colp = &sq[d*PIX + lx];
        int cnt = nly + KS - 1;
        float v[HW];
        #pragma unroll
        for (int i = 0; i < HW; ++i) v[i] = (i < cnt) ? colp[(ly0+i)*HW] : 0.f;
        float s = 0.f;
        #pragma unroll
        for (int j = 0; j < KS; ++j) s += v[j];
        #pragma unroll
        for (int o = 0; o < HP; ++o){
            if (o < nly) colp[(ly0+o)*HW] = s;
            if (o+1 < HP) s += v[o+KS] - v[o];
        }
    }
    __syncthreads();

    // per-output max over this block's dx set, one atomicMax per p
    for (int t = tid; t < HP*HP; t += 512){
        int py = t / HP, px = t - (t/HP)*HP;
        int ly = py - dy;
        if (ly < 0 || ly >= HP) continue;
        float m = -3.0e38f;
        bool any = false;
        #pragma unroll
        for (int d = 0; d < NDX; ++d){
            int dx = dxlo + d;
            int lx = px - dx;
            if (dx <= 29 && lx >= 0 && lx < HP){
                float v = sq[d*PIX + ly*HW + lx] * sinv[ly*HP + lx];
                m = fmaxf(m, v);
                any = true;
            }
        }
        if (any) atomicMax(&eout[t], encf(m));
    }
    __syncthreads();   // sq free for next pass
}

// ---------------- K1: paired-dy correlation, barrier-free mainloop ----------------
// grid: (4 dx-groups, 30 dy-pairs, 4 batch), 512 threads
__global__ void __launch_bounds__(512, 1) corr_kernel(const float* __restrict__ im1){
    extern __shared__ float smem[];
    float* sq   = smem;                  // [NDX*1600]
    float* sinv = sq + NDX*PIX;          // [900]

    int tid = threadIdx.x;
    int gx  = blockIdx.x;
    int p   = blockIdx.y;
    int b   = blockIdx.z;
    int dxlo = -29 + NDX*gx;

    int dyA, dyB, cntA, cntB;
    if (p < 29){ dyA = p - 29; dyB = p + 1; cntA = (11+p)*10; cntB = (39-p)*10; }
    else       { dyA = 0;      dyB = 0;     cntA = 400;       cntB = 0;        }

    for (int i = tid; i < HP*HP; i += 512) sinv[i] = g_inv[b*HP*HP + i];

    bool act = tid < cntA + cntB;
    int myDy, s;
    if (tid < cntA){ myDy = dyA; s = tid; } else { myDy = dyB; s = tid - cntA; }
    int y0t = (myDy < 0) ? -myDy : 0;
    int sy = y0t + s/10;
    int sx = (s - (s/10)*10)*4;
    int i1 = sy*HW + sx;

    const float* g1c = im1 + (size_t)b*NC*PIX + i1;
    // guarded im2 window base (16B aligned: sx, dxlo-SH, row offsets all mult of 4)
    const float* wbase = g_im2g + GUARD + (size_t)b*NC*PIX + (sy + myDy)*HW + sx + dxlo;

    float q[NDX*4];
    #pragma unroll
    for (int i = 0; i < NDX*4; ++i) q[i] = 0.f;

    if (act){
        switch (gx){
            case 0: run_channels<3>(g1c, wbase-3, q); break;
            case 1: run_channels<6>(g1c, wbase-6, q); break;
            case 2: run_channels<5>(g1c, wbase-5, q); break;
            default: run_channels<4>(g1c, wbase-4, q); break;
        }
    }

    unsigned* eout = &g_enc[b*HP*HP];
    do_epi(sq, sinv, eout, q, tid < cntA, i1, dyA, dxlo, tid);
    if (cntB > 0)
        do_epi(sq, sinv, eout, q, act && tid >= cntA, i1, dyB, dxlo, tid);
}

// ---------------- K2: decode ----------------
__global__ void decode_kernel(float* __restrict__ out){
    int t = blockIdx.x*blockDim.x + threadIdx.x;
    if (t < OUTN){
        unsigned e = g_enc[t];
        int v = (e & 0x80000000u) ? (int)(e ^ 0x80000000u) : ~(int)e;
        out[t] = __int_as_float(v);
    }
}

extern "C" void kernel_launch(void* const* d_in, const int* in_sizes, int n_in,
                              void* d_out, int out_size){
    (void)in_sizes; (void)n_in; (void)out_size;
    const float* im1 = (const float*)d_in[0];
    const float* im2 = (const float*)d_in[1];

    const int smem_bytes = (NDX*PIX + HP*HP) * (int)sizeof(float);
    cudaFuncSetAttribute(corr_kernel, cudaFuncAttributeMaxDynamicSharedMemorySize, smem_bytes);

    prep_kernel<<<64, 256>>>(im1, im2);
    norm_reduce<<<NB, 1024>>>();
    corr_kernel<<<dim3(4, 30, NB), 512, smem_bytes>>>(im1);
    decode_kernel<<<(OUTN + 255)/256, 256>>>((float*)d_out);
}